// round 11
// baseline (speedup 1.0000x reference)
#include <cuda_runtime.h>
#include <cstdint>
#include <cstddef>

typedef unsigned long long u64;
typedef unsigned int u32;

#define NN   4096
#define DIM  320
#define KP0  3686
#define KP1  2580
#define MP0  3712
#define MP1  2688

#define KB_A (NN/8)
#define KB_1 (MP0/8)
#define KB_2 (MP1/8)
#define KB_D (DIM/8)

#define OFF_START (NN*DIM)
#define OFF_POOL  (2*NN*DIM)

// ---------------- scratch (device globals; zero-initialized) ------------------
__device__ __align__(16) float g_AFh[(size_t)NN*NN];
__device__ __align__(16) float g_AFl[(size_t)NN*NN];
__device__ __align__(16) float g_G1h[(size_t)MP0*MP0];
__device__ __align__(16) float g_G1l[(size_t)MP0*MP0];
__device__ __align__(16) float g_U1h[(size_t)NN*MP0];
__device__ __align__(16) float g_U1l[(size_t)NN*MP0];
__device__ __align__(16) float g_G2h[(size_t)MP1*MP1];
__device__ __align__(16) float g_G2l[(size_t)MP1*MP1];
__device__ __align__(16) float g_U0h[(size_t)MP0*MP1];
__device__ __align__(16) float g_U0l[(size_t)MP0*MP1];
__device__ __align__(16) float g_BFh[(size_t)NN*DIM];
__device__ __align__(16) float g_BFl[(size_t)NN*DIM];
__device__ __align__(16) float g_XAh[(size_t)MP0*DIM];
__device__ __align__(16) float g_XAl[(size_t)MP0*DIM];
__device__ __align__(16) float g_XBh[(size_t)MP0*DIM];
__device__ __align__(16) float g_XBl[(size_t)MP0*DIM];
__device__ __align__(16) float g_P[(size_t)4*NN*DIM];
__device__ __align__(16) float g_Q[(size_t)4*NN*DIM];
__device__ __align__(16) float g_AXc[(size_t)4*NN*2*DIM];
__device__ __align__(16) float g_X0[NN*DIM];
__device__ __align__(16) float g_Xd0[NN*DIM];
__device__ __align__(16) float g_Xd1[KP0*DIM];
__device__ __align__(16) float g_Xp0[KP0*DIM];
__device__ __align__(16) float g_Xp1[KP1*DIM];
__device__ __align__(16) float g_Xb[KP1*DIM];
__device__ __align__(16) float g_Xu[KP0*DIM];
__device__ __align__(16) float g_XcL[NN*DIM];
__device__ float g_scores[NN];
__device__ int   g_idx0[NN];
__device__ float g_val0[NN];
__device__ int   g_idx1[NN];
__device__ float g_val1[NN];
__device__ int   g_idx01[KP1];

// ---------------- helpers ------------------------------------------------------
__device__ __forceinline__ void tf32split(float v, float& h, float& l) {
    u32 hb;
    asm("cvt.rna.tf32.f32 %0, %1;" : "=r"(hb) : "f"(v));
    h = __uint_as_float(hb);
    u32 lb;
    float res = v - h;
    asm("cvt.rna.tf32.f32 %0, %1;" : "=r"(lb) : "f"(res));
    l = __uint_as_float(lb);
}

#define MMA8(d, a, b) \
    asm volatile("mma.sync.aligned.m16n8k8.row.col.f32.tf32.tf32.f32 " \
        "{%0,%1,%2,%3}, {%4,%5,%6,%7}, {%8,%9}, {%0,%1,%2,%3};" \
        : "+f"((d)[0]), "+f"((d)[1]), "+f"((d)[2]), "+f"((d)[3]) \
        : "r"((a).x), "r"((a).y), "r"((a).z), "r"((a).w), "r"((b).x), "r"((b).y))

// ---------------- A-fragment conversion: row-staged + tf32 split --------------
// One block per output row m. Stages the source row coalesced in smem, then
// writes m16n8k8 A fragments: slot = ((mb*KB8+kb)*32 + g*4 + t)*4 + hi + 2*rsel,
// k = kb*8 + t + 4*rsel.  (Layout identical to the R9 afrag that passed.)
__global__ void afragRowT(const float* __restrict__ src, int lda,
                          const int* __restrict__ ridx, const int* __restrict__ cidx,
                          int Kv, int KB8,
                          float* __restrict__ oh, float* __restrict__ ol)
{
    __shared__ float row[NN];
    int m = blockIdx.x;
    int rr = ridx ? ridx[m] : m;
    const float* sp = src + (size_t)rr * lda;
    for (int i = threadIdx.x; i < lda; i += blockDim.x) row[i] = sp[i];
    __syncthreads();
    int mb = m >> 4;
    int g = m & 7;
    int hi = (m >> 3) & 1;
    int nslots = KB8 * 8;
    for (int s = threadIdx.x; s < nslots; s += blockDim.x) {
        int kb = s >> 3;
        int t = s & 3;
        int rsel = (s >> 2) & 1;
        int k = kb * 8 + t + 4 * rsel;
        float v = 0.f;
        if (k < Kv) v = row[cidx ? cidx[k] : k];
        float h, l;
        tf32split(v, h, l);
        size_t slot = (((size_t)mb * KB8 + kb) * 32 + g * 4 + t) * 4 + hi + 2 * rsel;
        oh[slot] = h;
        ol[slot] = l;
    }
}

// ---------------- B-fragment conversion (R9, proven) ---------------------------
// slot = ((nb*KB8+kb)*32+lane)*2+r; b0,b1 of m16n8k8 col-major B.
// mode 0: B[k][n] = src[k*lda + n] (pad k>=Kv). mode 1: B[k][n] = src[n*lda + k] (pad n>=Kv).
__global__ void bfrag(const float* __restrict__ src, int lda, int Kv, int KB8, int mode,
                      float* __restrict__ oh, float* __restrict__ ol, long long total)
{
    long long i = (long long)blockIdx.x * 256 + threadIdx.x;
    if (i >= total) return;
    int r = (int)(i & 1);
    int lane = (int)((i >> 1) & 31);
    long long f = i >> 6;
    int kb = (int)(f % KB8);
    int nb = (int)(f / KB8);
    int g = lane >> 2;
    int t = lane & 3;
    int k = kb * 8 + t + r * 4;
    int n = nb * 8 + g;
    float v = 0.f;
    if (mode == 0) {
        if (k < Kv) v = __ldg(&src[(size_t)k * lda + n]);
    } else {
        if (n < Kv) v = __ldg(&src[(size_t)n * lda + k]);
    }
    float h, l;
    tf32split(v, h, l);
    oh[i] = h;
    ol[i] = l;
}

// ---------------- 3xTF32 mma GEMM, N-tile 320 (A read once) --------------------
// CTA 64 x 320, 8 warps (2 M-groups x 4 N-groups), warp tile 32 x 80.
// split-K over grid.z: kb in [z*cps, min(+cps,KB8)), slice at C + z*cSlice.
__global__ void __launch_bounds__(256)
gemm_mma320t(const float* __restrict__ Ah, const float* __restrict__ Al,
             const float* __restrict__ Bh, const float* __restrict__ Bl,
             int KB8, float* __restrict__ C, int ldc, long long cSlice,
             int M, int cps)
{
    int lane = threadIdx.x & 31;
    int wid = threadIdx.x >> 5;
    int wm = wid & 1;
    int wn = wid >> 1;
    int mbB = blockIdx.y * 4 + wm * 2;
    int nbB = wn * 10;
    int kb0 = blockIdx.z * cps;
    int kb1 = kb0 + cps;
    if (kb1 > KB8) kb1 = KB8;
    C += (long long)blockIdx.z * cSlice;

    float acc[2][10][4];
#pragma unroll
    for (int i = 0; i < 2; i++)
#pragma unroll
        for (int j = 0; j < 10; j++)
#pragma unroll
            for (int r = 0; r < 4; r++) acc[i][j][r] = 0.f;

    for (int kb = kb0; kb < kb1; kb++) {
        uint4 ah[2];
        uint4 al[2];
#pragma unroll
        for (int i = 0; i < 2; i++) {
            size_t o = ((size_t)(mbB + i) * KB8 + kb) * 128 + lane * 4;
            ah[i] = *reinterpret_cast<const uint4*>(Ah + o);
            al[i] = *reinterpret_cast<const uint4*>(Al + o);
        }
#pragma unroll
        for (int j = 0; j < 10; j++) {
            size_t ob = ((size_t)(nbB + j) * KB8 + kb) * 64 + lane * 2;
            uint2 bh = *reinterpret_cast<const uint2*>(Bh + ob);
            uint2 bl = *reinterpret_cast<const uint2*>(Bl + ob);
#pragma unroll
            for (int i = 0; i < 2; i++) {
                MMA8(acc[i][j], ah[i], bh);
                MMA8(acc[i][j], ah[i], bl);
                MMA8(acc[i][j], al[i], bh);
            }
        }
    }

    int g = lane >> 2;
    int t = lane & 3;
#pragma unroll
    for (int i = 0; i < 2; i++) {
#pragma unroll
        for (int j = 0; j < 10; j++) {
            int m0 = (mbB + i) * 16 + g;
            int n0 = (nbB + j) * 8 + 2 * t;
            if (m0 < M) {
                C[(size_t)m0 * ldc + n0] = acc[i][j][0];
                C[(size_t)m0 * ldc + n0 + 1] = acc[i][j][1];
            }
            if (m0 + 8 < M) {
                C[(size_t)(m0 + 8) * ldc + n0] = acc[i][j][2];
                C[(size_t)(m0 + 8) * ldc + n0 + 1] = acc[i][j][3];
            }
        }
    }
}

// ---------------- 3xTF32 mma GEMM, tile 128x64 (pool; R9 proven) ---------------
__global__ void __launch_bounds__(128)
gemm_mma(const float* __restrict__ Ah, const float* __restrict__ Al,
         const float* __restrict__ Bh, const float* __restrict__ Bl,
         int KB8, float* __restrict__ C, int ldc, long long cSlice,
         int M, int Nout, int cps)
{
    int lane = threadIdx.x & 31;
    int wid = threadIdx.x >> 5;
    int wm = wid & 1;
    int wn = wid >> 1;
    int mbB = blockIdx.y * 8 + wm * 4;
    int nbB = blockIdx.x * 8 + wn * 4;
    int kb0 = blockIdx.z * cps;
    int kb1 = kb0 + cps;
    if (kb1 > KB8) kb1 = KB8;
    C += (long long)blockIdx.z * cSlice;

    float acc[4][4][4];
#pragma unroll
    for (int i = 0; i < 4; i++)
#pragma unroll
        for (int j = 0; j < 4; j++)
#pragma unroll
            for (int r = 0; r < 4; r++) acc[i][j][r] = 0.f;

    for (int kb = kb0; kb < kb1; kb++) {
        uint4 ah[4];
        uint4 al[4];
        uint2 bh[4];
        uint2 bl[4];
#pragma unroll
        for (int i = 0; i < 4; i++) {
            size_t o = ((size_t)(mbB + i) * KB8 + kb) * 128 + lane * 4;
            ah[i] = *reinterpret_cast<const uint4*>(Ah + o);
            al[i] = *reinterpret_cast<const uint4*>(Al + o);
        }
#pragma unroll
        for (int j = 0; j < 4; j++) {
            size_t o = ((size_t)(nbB + j) * KB8 + kb) * 64 + lane * 2;
            bh[j] = *reinterpret_cast<const uint2*>(Bh + o);
            bl[j] = *reinterpret_cast<const uint2*>(Bl + o);
        }
#pragma unroll
        for (int i = 0; i < 4; i++) {
#pragma unroll
            for (int j = 0; j < 4; j++) {
                MMA8(acc[i][j], ah[i], bh[j]);
                MMA8(acc[i][j], ah[i], bl[j]);
                MMA8(acc[i][j], al[i], bh[j]);
            }
        }
    }

    int g = lane >> 2;
    int t = lane & 3;
#pragma unroll
    for (int i = 0; i < 4; i++) {
#pragma unroll
        for (int j = 0; j < 4; j++) {
            int m0 = (mbB + i) * 16 + g;
            int n0 = (nbB + j) * 8 + 2 * t;
            if (m0 < M) {
                if (n0 < Nout) C[(size_t)m0 * ldc + n0] = acc[i][j][0];
                if (n0 + 1 < Nout) C[(size_t)m0 * ldc + n0 + 1] = acc[i][j][1];
            }
            if (m0 + 8 < M) {
                if (n0 < Nout) C[(size_t)(m0 + 8) * ldc + n0] = acc[i][j][2];
                if (n0 + 1 < Nout) C[(size_t)(m0 + 8) * ldc + n0 + 1] = acc[i][j][3];
            }
        }
    }
}

// ---------------- SIMT feature GEMM (proven R4) --------------------------------
__device__ __forceinline__ void ffma2(u64& c, u64 a, u64 b) {
    asm("fma.rn.f32x2 %0, %1, %2, %0;" : "+l"(c) : "l"(a), "l"(b));
}
__device__ __forceinline__ u64 dup2(float x) {
    u64 r;
    asm("mov.b64 %0, {%1, %1};" : "=l"(r) : "f"(x));
    return r;
}
__global__ void __launch_bounds__(128, 4)
gemmBig(const float* __restrict__ A, long long sliceA, int nSl, int lda,
        const float* __restrict__ B, int ldb,
        float* __restrict__ C, int ldc, long long partStride,
        int M, int kChunk, int K)
{
    __shared__ float As[2][16][128];
    __shared__ float Bs[2][16][64];
    int tid = threadIdx.x;
    int tx = tid & 7;
    int ty = tid >> 3;
    int bm0 = blockIdx.y * 128;
    int bn0 = blockIdx.x * 64;
    int kb = blockIdx.z * kChunk;
    int ke = kb + kChunk;
    if (ke > K) ke = K;
    int T = (ke - kb) >> 4;
    C += (long long)blockIdx.z * partStride;
    int a_r = tid >> 2;
    int a_k = (tid & 3) * 4;
    int b_r = tid >> 4;
    int b_c = (tid & 15) * 4;

    u64 acc[8][4];
#pragma unroll
    for (int i = 0; i < 8; i++) {
#pragma unroll
        for (int j = 0; j < 4; j++) acc[i][j] = 0ull;
    }

    float4 ra[4];
    float4 rb[2];
    auto loadT = [&](int t) {
        long long kOff = (long long)kb + t * 16;
#pragma unroll
        for (int p = 0; p < 4; p++) {
            int gm = bm0 + a_r + 32 * p;
            float4 v = make_float4(0.f, 0.f, 0.f, 0.f);
            if (gm < M) {
                const float* ptr = A + (size_t)gm * lda + kOff + a_k;
                v = *reinterpret_cast<const float4*>(ptr);
                for (int s = 1; s < nSl; s++) {
                    float4 w = *reinterpret_cast<const float4*>(ptr + (size_t)s * sliceA);
                    v.x += w.x; v.y += w.y; v.z += w.z; v.w += w.w;
                }
            }
            ra[p] = v;
        }
#pragma unroll
        for (int p = 0; p < 2; p++) {
            rb[p] = *reinterpret_cast<const float4*>(B + (size_t)(kOff + b_r + 8 * p) * ldb + bn0 + b_c);
        }
    };
    auto stage = [&](int buf) {
#pragma unroll
        for (int p = 0; p < 4; p++) {
            int r = a_r + 32 * p;
            As[buf][a_k + 0][r] = ra[p].x;
            As[buf][a_k + 1][r] = ra[p].y;
            As[buf][a_k + 2][r] = ra[p].z;
            As[buf][a_k + 3][r] = ra[p].w;
        }
#pragma unroll
        for (int p = 0; p < 2; p++) {
            *reinterpret_cast<float4*>(&Bs[buf][b_r + 8 * p][b_c]) = rb[p];
        }
    };
    if (T > 0) {
        loadT(0);
        stage(0);
        __syncthreads();
        if (T > 1) loadT(1);
    }
    for (int t = 0; t < T; t++) {
        int buf = t & 1;
#pragma unroll
        for (int kk = 0; kk < 16; kk++) {
            ulonglong2 b01 = *reinterpret_cast<const ulonglong2*>(&Bs[buf][kk][tx * 8]);
            ulonglong2 b23 = *reinterpret_cast<const ulonglong2*>(&Bs[buf][kk][tx * 8 + 4]);
            float4 a03 = *reinterpret_cast<const float4*>(&As[buf][kk][ty * 8]);
            float4 a47 = *reinterpret_cast<const float4*>(&As[buf][kk][ty * 8 + 4]);
            u64 d0 = dup2(a03.x);
            u64 d1 = dup2(a03.y);
            u64 d2 = dup2(a03.z);
            u64 d3 = dup2(a03.w);
            u64 d4 = dup2(a47.x);
            u64 d5 = dup2(a47.y);
            u64 d6 = dup2(a47.z);
            u64 d7 = dup2(a47.w);
            ffma2(acc[0][0], d0, b01.x); ffma2(acc[0][1], d0, b01.y); ffma2(acc[0][2], d0, b23.x); ffma2(acc[0][3], d0, b23.y);
            ffma2(acc[1][0], d1, b01.x); ffma2(acc[1][1], d1, b01.y); ffma2(acc[1][2], d1, b23.x); ffma2(acc[1][3], d1, b23.y);
            ffma2(acc[2][0], d2, b01.x); ffma2(acc[2][1], d2, b01.y); ffma2(acc[2][2], d2, b23.x); ffma2(acc[2][3], d2, b23.y);
            ffma2(acc[3][0], d3, b01.x); ffma2(acc[3][1], d3, b01.y); ffma2(acc[3][2], d3, b23.x); ffma2(acc[3][3], d3, b23.y);
            ffma2(acc[4][0], d4, b01.x); ffma2(acc[4][1], d4, b01.y); ffma2(acc[4][2], d4, b23.x); ffma2(acc[4][3], d4, b23.y);
            ffma2(acc[5][0], d5, b01.x); ffma2(acc[5][1], d5, b01.y); ffma2(acc[5][2], d5, b23.x); ffma2(acc[5][3], d5, b23.y);
            ffma2(acc[6][0], d6, b01.x); ffma2(acc[6][1], d6, b01.y); ffma2(acc[6][2], d6, b23.x); ffma2(acc[6][3], d6, b23.y);
            ffma2(acc[7][0], d7, b01.x); ffma2(acc[7][1], d7, b01.y); ffma2(acc[7][2], d7, b23.x); ffma2(acc[7][3], d7, b23.y);
        }
        if (t + 1 < T) {
            stage(buf ^ 1);
            __syncthreads();
            if (t + 2 < T) loadT(t + 2);
        }
    }
#pragma unroll
    for (int i = 0; i < 8; i++) {
        int m = bm0 + ty * 8 + i;
        if (m < M) {
            float* cp = C + (size_t)m * ldc + bn0 + tx * 8;
            ulonglong2 v0;
            v0.x = acc[i][0];
            v0.y = acc[i][1];
            ulonglong2 v1;
            v1.x = acc[i][2];
            v1.y = acc[i][3];
            *reinterpret_cast<ulonglong2*>(cp) = v0;
            *reinterpret_cast<ulonglong2*>(cp + 4) = v1;
        }
    }
}

// ---------------- epilogue / small kernels -------------------------------------
__global__ void epilogue(const float* __restrict__ T, long long sliceT,
                         const float* __restrict__ bias, const float* __restrict__ R,
                         float* __restrict__ dst, int n)
{
    int i = blockIdx.x * 256 + threadIdx.x;
    if (i >= n * DIM) return;
    int c = i % DIM;
    float v = T[i] + T[i + sliceT] + T[i + 2 * sliceT] + T[i + 3 * sliceT] + bias[c];
    v = v > 0.f ? v : 0.f;
    if (R) v += R[i];
    dst[i] = v;
}
__global__ void pooldiag(float* __restrict__ out)
{
    int i = blockIdx.x * 256 + threadIdx.x;
    if (i < KP0) out[(size_t)i * KP0 + i] = 1.0f;
}
__global__ void scores_kernel(const float* __restrict__ X, int n,
                              const float* __restrict__ pw, const float* __restrict__ pb,
                              float* __restrict__ out)
{
    int row = blockIdx.x * 8 + (threadIdx.x >> 5);
    int lane = threadIdx.x & 31;
    if (row >= n) return;
    float s = 0.f;
    for (int c = lane; c < DIM; c += 32) s += X[(size_t)row * DIM + c] * pw[c];
#pragma unroll
    for (int o = 16; o > 0; o >>= 1) s += __shfl_down_sync(0xffffffffu, s, o);
    if (lane == 0) {
        float z = (s + pb[0]) * 0.01f;
        out[row] = 1.0f / (1.0f + expf(-z));
    }
}
__global__ void topk_sort(const float* __restrict__ scores, int n,
                          int* __restrict__ idx_out, float* __restrict__ val_out)
{
    __shared__ unsigned long long keys[4096];
    int tid = threadIdx.x;
    for (int i = tid; i < 4096; i += 1024) {
        unsigned long long k = 0ull;
        if (i < n) {
            unsigned int fb = __float_as_uint(scores[i]);
            k = ((unsigned long long)fb << 12) | (unsigned int)(4095 - i);
        }
        keys[i] = k;
    }
    __syncthreads();
    for (int k = 2; k <= 4096; k <<= 1) {
        for (int j = k >> 1; j > 0; j >>= 1) {
            for (int t = tid; t < 4096; t += 1024) {
                int ixj = t ^ j;
                if (ixj > t) {
                    bool desc = ((t & k) == 0);
                    unsigned long long a = keys[t];
                    unsigned long long b = keys[ixj];
                    if ((a < b) == desc) {
                        keys[t] = b;
                        keys[ixj] = a;
                    }
                }
            }
            __syncthreads();
        }
    }
    for (int i = tid; i < 4096; i += 1024) {
        unsigned long long kk = keys[i];
        idx_out[i] = 4095 - (int)(kk & 0xFFFull);
        val_out[i] = __uint_as_float((unsigned int)(kk >> 12));
    }
}
__global__ void gather_scale(const float* __restrict__ X, const int* __restrict__ idx,
                             const float* __restrict__ vals, float* __restrict__ out, int kn)
{
    int i = blockIdx.x * 256 + threadIdx.x;
    if (i >= kn * DIM) return;
    int r = i / DIM;
    int c = i - r * DIM;
    out[i] = X[(size_t)idx[r] * DIM + c] * vals[r];
}
__global__ void compose_idx(const int* __restrict__ a, const int* __restrict__ b,
                            int* __restrict__ out, int n)
{
    int i = blockIdx.x * 256 + threadIdx.x;
    if (i < n) out[i] = a[b[i]];
}

// -----------------------------------------------------------------------------
extern "C" void kernel_launch(void* const* d_in, const int* in_sizes, int n_in,
                              void* d_out, int out_size)
{
    const float* A = (const float*)d_in[0];
    const float* X = (const float*)d_in[1];
    const float* w_start = (const float*)d_in[2];
    const float* b_start = (const float*)d_in[3];
    const float* w_down0 = (const float*)d_in[4];
    const float* b_down0 = (const float*)d_in[5];
    const float* w_down1 = (const float*)d_in[6];
    const float* b_down1 = (const float*)d_in[7];
    const float* p_w0 = (const float*)d_in[8];
    const float* p_b0 = (const float*)d_in[9];
    const float* p_w1 = (const float*)d_in[10];
    const float* p_b1 = (const float*)d_in[11];
    const float* w_bottom = (const float*)d_in[12];
    const float* b_bottom = (const float*)d_in[13];
    const float* w_up0 = (const float*)d_in[14];
    const float* b_up0 = (const float*)d_in[15];
    const float* w_up1 = (const float*)d_in[16];
    const float* b_up1 = (const float*)d_in[17];
    const float* w_end = (const float*)d_in[18];
    const float* b_end = (const float*)d_in[19];
    float* out = (float*)d_out;

    float *AFh, *AFl, *G1h, *G1l, *U1h, *U1l, *G2h, *G2l, *U0h, *U0l;
    float *BFh, *BFl, *XAh, *XAl, *XBh, *XBl;
    float *P, *Q, *AXc, *X0, *Xd0, *Xd1, *Xp0, *Xp1, *Xb, *Xu, *XcL;
    float *sc, *v0, *v1;
    int *i0, *i1, *i01;
    cudaGetSymbolAddress((void**)&AFh, g_AFh);
    cudaGetSymbolAddress((void**)&AFl, g_AFl);
    cudaGetSymbolAddress((void**)&G1h, g_G1h);
    cudaGetSymbolAddress((void**)&G1l, g_G1l);
    cudaGetSymbolAddress((void**)&U1h, g_U1h);
    cudaGetSymbolAddress((void**)&U1l, g_U1l);
    cudaGetSymbolAddress((void**)&G2h, g_G2h);
    cudaGetSymbolAddress((void**)&G2l, g_G2l);
    cudaGetSymbolAddress((void**)&U0h, g_U0h);
    cudaGetSymbolAddress((void**)&U0l, g_U0l);
    cudaGetSymbolAddress((void**)&BFh, g_BFh);
    cudaGetSymbolAddress((void**)&BFl, g_BFl);
    cudaGetSymbolAddress((void**)&XAh, g_XAh);
    cudaGetSymbolAddress((void**)&XAl, g_XAl);
    cudaGetSymbolAddress((void**)&XBh, g_XBh);
    cudaGetSymbolAddress((void**)&XBl, g_XBl);
    cudaGetSymbolAddress((void**)&P, g_P);
    cudaGetSymbolAddress((void**)&Q, g_Q);
    cudaGetSymbolAddress((void**)&AXc, g_AXc);
    cudaGetSymbolAddress((void**)&X0, g_X0);
    cudaGetSymbolAddress((void**)&Xd0, g_Xd0);
    cudaGetSymbolAddress((void**)&Xd1, g_Xd1);
    cudaGetSymbolAddress((void**)&Xp0, g_Xp0);
    cudaGetSymbolAddress((void**)&Xp1, g_Xp1);
    cudaGetSymbolAddress((void**)&Xb, g_Xb);
    cudaGetSymbolAddress((void**)&Xu, g_Xu);
    cudaGetSymbolAddress((void**)&XcL, g_XcL);
    cudaGetSymbolAddress((void**)&sc, g_scores);
    cudaGetSymbolAddress((void**)&i0, g_idx0);
    cudaGetSymbolAddress((void**)&v0, g_val0);
    cudaGetSymbolAddress((void**)&i1, g_idx1);
    cudaGetSymbolAddress((void**)&v1, g_val1);
    cudaGetSymbolAddress((void**)&i01, g_idx01);

    const long long PS = (long long)NN * DIM;
    const long long PSX = (long long)NN * 2 * DIM;

    auto tg = [](long long n) { return (unsigned)((n + 255) / 256); };
    auto mg = [&](const float* ah, const float* al, const float* bh, const float* bl,
                  int KB8, float* C, int ldc, long long cSlice, int M) {
        int cps = (KB8 + 3) / 4;
        dim3 g(1, (unsigned)((M + 63) / 64), 4);
        gemm_mma320t<<<g, 256>>>(ah, al, bh, bl, KB8, C, ldc, cSlice, M, cps);
    };
    auto fg = [&](const float* A_, long long sA, int nSl, int lda, const float* B_,
                  float* C_, int M_, int K_) {
        int kChunk = (((K_ + 3) / 4 + 15) / 16) * 16;
        dim3 g(5, (unsigned)((M_ + 127) / 128), 4);
        gemmBig<<<g, 128>>>(A_, sA, nSl, lda, B_, DIM, C_, DIM, PS, M_, kChunk, K_);
    };
    auto eg = [](int n) { return (unsigned)((n * DIM + 255) / 256); };

    const long long totBF512 = (long long)NN * DIM;
    const long long totBF464 = (long long)MP0 * DIM;
    const long long totBF336 = (long long)MP1 * DIM;
    const long long totXB = (long long)MP0 * DIM;

    // one-time: A fragments (row-staged), X B-fragments
    afragRowT<<<NN, 256>>>(A, NN, nullptr, nullptr, NN, KB_A, AFh, AFl);
    bfrag<<<tg(totBF512), 256>>>(X, DIM, NN, KB_A, 0, BFh, BFl, totBF512);

    // start: X0 = relu((A@X)@w_start + b)
    mg(AFh, AFl, BFh, BFl, KB_A, P, DIM, PS, NN);
    fg(P, PS, 4, DIM, w_start, Q, NN, DIM);
    epilogue<<<eg(NN), 256>>>(Q, PS, b_start, nullptr, X0, NN);
    cudaMemcpyAsync(out + OFF_START, X0, (size_t)NN * DIM * sizeof(float),
                    cudaMemcpyDeviceToDevice, 0);

    // Xd0 = gcn(A, X0, w_down0); A@X0 slices kept in AXc right half
    bfrag<<<tg(totBF512), 256>>>(X0, DIM, NN, KB_A, 0, BFh, BFl, totBF512);
    mg(AFh, AFl, BFh, BFl, KB_A, AXc + DIM, 2 * DIM, PSX, NN);
    fg(AXc + DIM, PSX, 4, 2 * DIM, w_down0, Q, NN, DIM);
    epilogue<<<eg(NN), 256>>>(Q, PS, b_down0, nullptr, Xd0, NN);

    // pool 0
    scores_kernel<<<(NN + 7) / 8, 256>>>(Xd0, NN, p_w0, p_b0, sc);
    topk_sort<<<1, 1024>>>(sc, NN, i0, v0);
    gather_scale<<<tg((long long)KP0 * DIM), 256>>>(Xd0, i0, v0, Xp0, KP0);
    afragRowT<<<KP0, 256>>>(A, NN, i0, i0, KP0, KB_1, G1h, G1l);
    afragRowT<<<NN, 256>>>(A, NN, nullptr, i0, KP0, KB_1, U1h, U1l);

    // Xd1 = gcn(A1, Xp0, w_down1)
    bfrag<<<tg(totBF464), 256>>>(Xp0, DIM, KP0, KB_1, 0, BFh, BFl, totBF464);
    mg(G1h, G1l, BFh, BFl, KB_1, P, DIM, PS, KP0);
    fg(P, PS, 4, DIM, w_down1, Q, KP0, DIM);
    epilogue<<<eg(KP0), 256>>>(Q, PS, b_down1, nullptr, Xd1, KP0);

    // pool frags for Xp0 @ Xp0^T (A-side row-staged, B-side transpose)
    afragRowT<<<KP0, 256>>>(Xp0, DIM, nullptr, nullptr, DIM, KB_D, XAh, XAl);
    bfrag<<<tg(totXB), 256>>>(Xp0, DIM, KP0, KB_D, 1, XBh, XBl, totXB);

    // pool 1
    scores_kernel<<<(KP0 + 7) / 8, 256>>>(Xd1, KP0, p_w1, p_b1, sc);
    topk_sort<<<1, 1024>>>(sc, KP0, i1, v1);
    gather_scale<<<tg((long long)KP1 * DIM), 256>>>(Xd1, i1, v1, Xp1, KP1);
    compose_idx<<<tg(KP1), 256>>>(i0, i1, i01, KP1);
    afragRowT<<<KP1, 256>>>(A, NN, i01, i01, KP1, KB_2, G2h, G2l);
    afragRowT<<<KP0, 256>>>(A, NN, i0, i01, KP1, KB_2, U0h, U0l);

    // bottom: Xb = gcn(A2, Xp1, w_bottom)
    bfrag<<<tg(totBF336), 256>>>(Xp1, DIM, KP1, KB_2, 0, BFh, BFl, totBF336);
    mg(G2h, G2l, BFh, BFl, KB_2, P, DIM, PS, KP1);
    fg(P, PS, 4, DIM, w_bottom, Q, KP1, DIM);
    epilogue<<<eg(KP1), 256>>>(Q, PS, b_bottom, nullptr, Xb, KP1);

    // up 0: Xu = gcn(A1, scatter(Xb), w_up0) + Xd1
    bfrag<<<tg(totBF336), 256>>>(Xb, DIM, KP1, KB_2, 0, BFh, BFl, totBF336);
    mg(U0h, U0l, BFh, BFl, KB_2, P, DIM, PS, KP0);
    fg(P, PS, 4, DIM, w_up0, Q, KP0, DIM);
    epilogue<<<eg(KP0), 256>>>(Q, PS, b_up0, Xd1, Xu, KP0);

    // up 1: XcL = gcn(A, scatter(Xu), w_up1) + Xd0
    bfrag<<<tg(totBF464), 256>>>(Xu, DIM, KP0, KB_1, 0, BFh, BFl, totBF464);
    mg(U1h, U1l, BFh, BFl, KB_1, P, DIM, PS, NN);
    fg(P, PS, 4, DIM, w_up1, Q, NN, DIM);
    epilogue<<<eg(NN), 256>>>(Q, PS, b_up1, Xd0, XcL, NN);

    // end: Xout = gcn(A, [XcL | X0], w_end); A@X0 reused from AXc right half
    bfrag<<<tg(totBF512), 256>>>(XcL, DIM, NN, KB_A, 0, BFh, BFl, totBF512);
    mg(AFh, AFl, BFh, BFl, KB_A, AXc, 2 * DIM, PSX, NN);
    fg(AXc, PSX, 4, 2 * DIM, w_end, Q, NN, 2 * DIM);
    epilogue<<<eg(NN), 256>>>(Q, PS, b_end, nullptr, out, NN);

    // pool_out = Xp0 @ Xp0^T, diag = 1
    {
        dim3 g((unsigned)((KP0 + 63) / 64), (unsigned)((KP0 + 127) / 128), 1);
        gemm_mma<<<g, 128>>>(XAh, XAl, XBh, XBl, KB_D, out + OFF_POOL, KP0, 0, KP0, KP0, KB_D);
    }
    pooldiag<<<tg(KP0), 256>>>(out + OFF_POOL);
}

// round 12
// speedup vs baseline: 2.2043x; 2.2043x over previous
#include <cuda_runtime.h>
#include <cuda_fp16.h>
#include <cstdint>
#include <cstddef>
#include <math.h>

typedef unsigned long long u64;
typedef unsigned int u32;

#define NN   4096
#define DIM  320
#define KP0  3686
#define KP1  2580
#define MP0  3712
#define MP1  2688

#define KB_A (NN/16)
#define KB_1 (MP0/16)
#define KB_2 (MP1/16)
#define KB_D (DIM/16)

#define OFF_START (NN*DIM)
#define OFF_POOL  (2*NN*DIM)

// ---------------- scratch (device globals; zero-initialized) ------------------
// fp16 fragments packed as u32 (2 halves each)
__device__ __align__(16) u32 g_AFh[(size_t)NN*NN/2];
__device__ __align__(16) u32 g_AFl[(size_t)NN*NN/2];
__device__ __align__(16) u32 g_G1h[(size_t)MP0*MP0/2];
__device__ __align__(16) u32 g_G1l[(size_t)MP0*MP0/2];
__device__ __align__(16) u32 g_U1h[(size_t)NN*MP0/2];
__device__ __align__(16) u32 g_U1l[(size_t)NN*MP0/2];
__device__ __align__(16) u32 g_G2h[(size_t)MP1*MP1/2];
__device__ __align__(16) u32 g_G2l[(size_t)MP1*MP1/2];
__device__ __align__(16) u32 g_U0h[(size_t)MP0*MP1/2];
__device__ __align__(16) u32 g_U0l[(size_t)MP0*MP1/2];
__device__ __align__(16) u32 g_BFh[(size_t)NN*DIM/2];
__device__ __align__(16) u32 g_BFl[(size_t)NN*DIM/2];
__device__ __align__(16) u32 g_XAh[(size_t)MP0*DIM/2];
__device__ __align__(16) u32 g_XAl[(size_t)MP0*DIM/2];
__device__ __align__(16) u32 g_XBh[(size_t)MP0*DIM/2];
__device__ __align__(16) u32 g_XBl[(size_t)MP0*DIM/2];
// fp32 intermediates
__device__ __align__(16) float g_P[(size_t)4*NN*DIM];
__device__ __align__(16) float g_Q[(size_t)4*NN*DIM];
__device__ __align__(16) float g_AXc[(size_t)4*NN*2*DIM];
__device__ __align__(16) float g_X0[NN*DIM];
__device__ __align__(16) float g_Xd0[NN*DIM];
__device__ __align__(16) float g_Xd1[KP0*DIM];
__device__ __align__(16) float g_Xp0[KP0*DIM];
__device__ __align__(16) float g_Xp1[KP1*DIM];
__device__ __align__(16) float g_Xb[KP1*DIM];
__device__ __align__(16) float g_Xu[KP0*DIM];
__device__ __align__(16) float g_XcL[NN*DIM];
__device__ u32   g_mx[8];
__device__ float g_scores[NN];
__device__ int   g_idx0[NN];
__device__ float g_val0[NN];
__device__ int   g_idx1[NN];
__device__ float g_val1[NN];
__device__ int   g_idx01[KP1];

// ---------------- scaling helpers ----------------------------------------------
__device__ __forceinline__ int shFromMax(const u32* mx) {
    if (!mx) return 0;
    float mv = __uint_as_float(*mx);
    if (!(mv > 0.f)) return 0;
    int e;
    frexpf(mv, &e);
    int sh = e - 8;
    return sh > 0 ? sh : 0;
}
__device__ __forceinline__ void splitpack(float v0, float v1, u32& hh, u32& ll) {
    __half h0 = __float2half_rn(v0);
    __half h1 = __float2half_rn(v1);
    __half l0 = __float2half_rn(v0 - __half2float(h0));
    __half l1 = __float2half_rn(v1 - __half2float(h1));
    hh = ((u32)__half_as_ushort(h1) << 16) | (u32)__half_as_ushort(h0);
    ll = ((u32)__half_as_ushort(l1) << 16) | (u32)__half_as_ushort(l0);
}

#define MMA16(d, a, b) \
    asm volatile("mma.sync.aligned.m16n8k16.row.col.f32.f16.f16.f32 " \
        "{%0,%1,%2,%3}, {%4,%5,%6,%7}, {%8,%9}, {%0,%1,%2,%3};" \
        : "+f"((d)[0]), "+f"((d)[1]), "+f"((d)[2]), "+f"((d)[3]) \
        : "r"((a).x), "r"((a).y), "r"((a).z), "r"((a).w), "r"((b).x), "r"((b).y))

// ---------------- absmax / zero --------------------------------------------------
__global__ void zeroMx(u32* mx)
{
    if (threadIdx.x < 8) mx[threadIdx.x] = 0u;
}
__global__ void absmaxK(const float* __restrict__ src, long long n, u32* __restrict__ out)
{
    long long i = (long long)blockIdx.x * 256 + threadIdx.x;
    u32 m = 0;
    for (long long j = i; j < n; j += (long long)gridDim.x * 256)
        m = max(m, __float_as_uint(fabsf(src[j])));
#pragma unroll
    for (int o = 16; o > 0; o >>= 1)
        m = max(m, __shfl_down_sync(0xffffffffu, m, o));
    if ((threadIdx.x & 31) == 0) atomicMax(out, m);
}

// ---------------- A-fragment conversion: row-staged + fp16 split ---------------
// One block per row m. m16n8k16 A slots (spec-checked):
// slot = ((mb*KB16+kb)*32 + g*4 + t)*4 + hi + 2*khalf ; k pair = kb*16 + 2t + 8*khalf.
__global__ void afragRow16(const float* __restrict__ src, int lda,
                           const int* __restrict__ ridx, const int* __restrict__ cidx,
                           int Kv, int KB16, const u32* __restrict__ mx,
                           u32* __restrict__ oh, u32* __restrict__ ol)
{
    __shared__ float row[NN];
    int m = blockIdx.x;
    int rr = ridx ? ridx[m] : m;
    const float* sp = src + (size_t)rr * lda;
    for (int i = threadIdx.x; i < lda; i += blockDim.x) row[i] = sp[i];
    __syncthreads();
    float s = exp2f((float)(-shFromMax(mx)));
    int mb = m >> 4;
    int g = m & 7;
    int hi = (m >> 3) & 1;
    int nslots = KB16 * 8;
    for (int sidx = threadIdx.x; sidx < nslots; sidx += blockDim.x) {
        int kb = sidx >> 3;
        int t = sidx & 3;
        int khalf = (sidx >> 2) & 1;
        int k0 = kb * 16 + 2 * t + 8 * khalf;
        int k1 = k0 + 1;
        float v0 = 0.f;
        float v1 = 0.f;
        if (k0 < Kv) v0 = row[cidx ? cidx[k0] : k0] * s;
        if (k1 < Kv) v1 = row[cidx ? cidx[k1] : k1] * s;
        u32 hh, ll;
        splitpack(v0, v1, hh, ll);
        size_t slot = (((size_t)mb * KB16 + kb) * 32 + g * 4 + t) * 4 + hi + 2 * khalf;
        oh[slot] = hh;
        ol[slot] = ll;
    }
}

// ---------------- B-fragment conversion (spec-checked) --------------------------
// slot = ((nb*KB16+kb)*32 + lane)*2 + khalf ; k pair = kb*16 + 2t + 8*khalf, col n.
// mode 0: B[k][n] = src[k*lda+n] (pad k>=Kv). mode 1: B[k][n] = src[n*lda+k] (pad n>=Kv).
__global__ void bfrag16(const float* __restrict__ src, int lda, int Kv, int KB16, int mode,
                        const u32* __restrict__ mx,
                        u32* __restrict__ oh, u32* __restrict__ ol, long long total)
{
    long long i = (long long)blockIdx.x * 256 + threadIdx.x;
    if (i >= total) return;
    float s = exp2f((float)(-shFromMax(mx)));
    int khalf = (int)(i & 1);
    int lane = (int)((i >> 1) & 31);
    long long f = i >> 6;
    int kb = (int)(f % KB16);
    int nb = (int)(f / KB16);
    int g = lane >> 2;
    int t = lane & 3;
    int k0 = kb * 16 + 2 * t + 8 * khalf;
    int k1 = k0 + 1;
    int n = nb * 8 + g;
    float v0 = 0.f;
    float v1 = 0.f;
    if (mode == 0) {
        if (k0 < Kv) v0 = __ldg(&src[(size_t)k0 * lda + n]) * s;
        if (k1 < Kv) v1 = __ldg(&src[(size_t)k1 * lda + n]) * s;
    } else {
        if (n < Kv) {
            v0 = __ldg(&src[(size_t)n * lda + k0]) * s;
            v1 = __ldg(&src[(size_t)n * lda + k1]) * s;
        }
    }
    u32 hh, ll;
    splitpack(v0, v1, hh, ll);
    oh[i] = hh;
    ol[i] = ll;
}

// ---------------- fp16 3-pass mma GEMM (R9 shape, k16) --------------------------
// CTA 128x64, 4 warps; warp 64x32 (4x4 frags). split-K over grid.z.
// Output unscaled by exp2(shA+shB).
__global__ void __launch_bounds__(128)
gemm_mma16(const u32* __restrict__ Ah, const u32* __restrict__ Al,
           const u32* __restrict__ Bh, const u32* __restrict__ Bl,
           int KB16, float* __restrict__ C, int ldc, long long cSlice,
           int M, int Nout, int cps,
           const u32* __restrict__ mxA, const u32* __restrict__ mxB)
{
    int lane = threadIdx.x & 31;
    int wid = threadIdx.x >> 5;
    int wm = wid & 1;
    int wn = wid >> 1;
    int mbB = blockIdx.y * 8 + wm * 4;
    int nbB = blockIdx.x * 8 + wn * 4;
    int kb0 = blockIdx.z * cps;
    int kb1 = kb0 + cps;
    if (kb1 > KB16) kb1 = KB16;
    C += (long long)blockIdx.z * cSlice;
    float oscale = exp2f((float)(shFromMax(mxA) + shFromMax(mxB)));

    float acc[4][4][4];
#pragma unroll
    for (int i = 0; i < 4; i++)
#pragma unroll
        for (int j = 0; j < 4; j++)
#pragma unroll
            for (int r = 0; r < 4; r++) acc[i][j][r] = 0.f;

    for (int kb = kb0; kb < kb1; kb++) {
        uint4 ah[4];
        uint4 al[4];
        uint2 bh[4];
        uint2 bl[4];
#pragma unroll
        for (int i = 0; i < 4; i++) {
            size_t o = ((size_t)(mbB + i) * KB16 + kb) * 128 + lane * 4;
            ah[i] = *reinterpret_cast<const uint4*>(Ah + o);
            al[i] = *reinterpret_cast<const uint4*>(Al + o);
        }
#pragma unroll
        for (int j = 0; j < 4; j++) {
            size_t o = ((size_t)(nbB + j) * KB16 + kb) * 64 + lane * 2;
            bh[j] = *reinterpret_cast<const uint2*>(Bh + o);
            bl[j] = *reinterpret_cast<const uint2*>(Bl + o);
        }
#pragma unroll
        for (int i = 0; i < 4; i++) {
#pragma unroll
            for (int j = 0; j < 4; j++) {
                MMA16(acc[i][j], ah[i], bh[j]);
                MMA16(acc[i][j], ah[i], bl[j]);
                MMA16(acc[i][j], al[i], bh[j]);
            }
        }
    }

    int g = lane >> 2;
    int t = lane & 3;
#pragma unroll
    for (int i = 0; i < 4; i++) {
#pragma unroll
        for (int j = 0; j < 4; j++) {
            int m0 = (mbB + i) * 16 + g;
            int n0 = (nbB + j) * 8 + 2 * t;
            if (m0 < M) {
                if (n0 < Nout) C[(size_t)m0 * ldc + n0] = acc[i][j][0] * oscale;
                if (n0 + 1 < Nout) C[(size_t)m0 * ldc + n0 + 1] = acc[i][j][1] * oscale;
            }
            if (m0 + 8 < M) {
                if (n0 < Nout) C[(size_t)(m0 + 8) * ldc + n0] = acc[i][j][2] * oscale;
                if (n0 + 1 < Nout) C[(size_t)(m0 + 8) * ldc + n0 + 1] = acc[i][j][3] * oscale;
            }
        }
    }
}

// ---------------- SIMT feature GEMM (proven R4) --------------------------------
__device__ __forceinline__ void ffma2(u64& c, u64 a, u64 b) {
    asm("fma.rn.f32x2 %0, %1, %2, %0;" : "+l"(c) : "l"(a), "l"(b));
}
__device__ __forceinline__ u64 dup2(float x) {
    u64 r;
    asm("mov.b64 %0, {%1, %1};" : "=l"(r) : "f"(x));
    return r;
}
__global__ void __launch_bounds__(128, 4)
gemmBig(const float* __restrict__ A, long long sliceA, int nSl, int lda,
        const float* __restrict__ B, int ldb,
        float* __restrict__ C, int ldc, long long partStride,
        int M, int kChunk, int K)
{
    __shared__ float As[2][16][128];
    __shared__ float Bs[2][16][64];
    int tid = threadIdx.x;
    int tx = tid & 7;
    int ty = tid >> 3;
    int bm0 = blockIdx.y * 128;
    int bn0 = blockIdx.x * 64;
    int kb = blockIdx.z * kChunk;
    int ke = kb + kChunk;
    if (ke > K) ke = K;
    int T = (ke - kb) >> 4;
    C += (long long)blockIdx.z * partStride;
    int a_r = tid >> 2;
    int a_k = (tid & 3) * 4;
    int b_r = tid >> 4;
    int b_c = (tid & 15) * 4;

    u64 acc[8][4];
#pragma unroll
    for (int i = 0; i < 8; i++) {
#pragma unroll
        for (int j = 0; j < 4; j++) acc[i][j] = 0ull;
    }

    float4 ra[4];
    float4 rb[2];
    auto loadT = [&](int t) {
        long long kOff = (long long)kb + t * 16;
#pragma unroll
        for (int p = 0; p < 4; p++) {
            int gm = bm0 + a_r + 32 * p;
            float4 v = make_float4(0.f, 0.f, 0.f, 0.f);
            if (gm < M) {
                const float* ptr = A + (size_t)gm * lda + kOff + a_k;
                v = *reinterpret_cast<const float4*>(ptr);
                for (int s = 1; s < nSl; s++) {
                    float4 w = *reinterpret_cast<const float4*>(ptr + (size_t)s * sliceA);
                    v.x += w.x; v.y += w.y; v.z += w.z; v.w += w.w;
                }
            }
            ra[p] = v;
        }
#pragma unroll
        for (int p = 0; p < 2; p++) {
            rb[p] = *reinterpret_cast<const float4*>(B + (size_t)(kOff + b_r + 8 * p) * ldb + bn0 + b_c);
        }
    };
    auto stage = [&](int buf) {
#pragma unroll
        for (int p = 0; p < 4; p++) {
            int r = a_r + 32 * p;
            As[buf][a_k + 0][r] = ra[p].x;
            As[buf][a_k + 1][r] = ra[p].y;
            As[buf][a_k + 2][r] = ra[p].z;
            As[buf][a_k + 3][r] = ra[p].w;
        }
#pragma unroll
        for (int p = 0; p < 2; p++) {
            *reinterpret_cast<float4*>(&Bs[buf][b_r + 8 * p][b_c]) = rb[p];
        }
    };
    if (T > 0) {
        loadT(0);
        stage(0);
        __syncthreads();
        if (T > 1) loadT(1);
    }
    for (int t = 0; t < T; t++) {
        int buf = t & 1;
#pragma unroll
        for (int kk = 0; kk < 16; kk++) {
            ulonglong2 b01 = *reinterpret_cast<const ulonglong2*>(&Bs[buf][kk][tx * 8]);
            ulonglong2 b23 = *reinterpret_cast<const ulonglong2*>(&Bs[buf][kk][tx * 8 + 4]);
            float4 a03 = *reinterpret_cast<const float4*>(&As[buf][kk][ty * 8]);
            float4 a47 = *reinterpret_cast<const float4*>(&As[buf][kk][ty * 8 + 4]);
            u64 d0 = dup2(a03.x);
            u64 d1 = dup2(a03.y);
            u64 d2 = dup2(a03.z);
            u64 d3 = dup2(a03.w);
            u64 d4 = dup2(a47.x);
            u64 d5 = dup2(a47.y);
            u64 d6 = dup2(a47.z);
            u64 d7 = dup2(a47.w);
            ffma2(acc[0][0], d0, b01.x); ffma2(acc[0][1], d0, b01.y); ffma2(acc[0][2], d0, b23.x); ffma2(acc[0][3], d0, b23.y);
            ffma2(acc[1][0], d1, b01.x); ffma2(acc[1][1], d1, b01.y); ffma2(acc[1][2], d1, b23.x); ffma2(acc[1][3], d1, b23.y);
            ffma2(acc[2][0], d2, b01.x); ffma2(acc[2][1], d2, b01.y); ffma2(acc[2][2], d2, b23.x); ffma2(acc[2][3], d2, b23.y);
            ffma2(acc[3][0], d3, b01.x); ffma2(acc[3][1], d3, b01.y); ffma2(acc[3][2], d3, b23.x); ffma2(acc[3][3], d3, b23.y);
            ffma2(acc[4][0], d4, b01.x); ffma2(acc[4][1], d4, b01.y); ffma2(acc[4][2], d4, b23.x); ffma2(acc[4][3], d4, b23.y);
            ffma2(acc[5][0], d5, b01.x); ffma2(acc[5][1], d5, b01.y); ffma2(acc[5][2], d5, b23.x); ffma2(acc[5][3], d5, b23.y);
            ffma2(acc[6][0], d6, b01.x); ffma2(acc[6][1], d6, b01.y); ffma2(acc[6][2], d6, b23.x); ffma2(acc[6][3], d6, b23.y);
            ffma2(acc[7][0], d7, b01.x); ffma2(acc[7][1], d7, b01.y); ffma2(acc[7][2], d7, b23.x); ffma2(acc[7][3], d7, b23.y);
        }
        if (t + 1 < T) {
            stage(buf ^ 1);
            __syncthreads();
            if (t + 2 < T) loadT(t + 2);
        }
    }
#pragma unroll
    for (int i = 0; i < 8; i++) {
        int m = bm0 + ty * 8 + i;
        if (m < M) {
            float* cp = C + (size_t)m * ldc + bn0 + tx * 8;
            ulonglong2 v0;
            v0.x = acc[i][0];
            v0.y = acc[i][1];
            ulonglong2 v1;
            v1.x = acc[i][2];
            v1.y = acc[i][3];
            *reinterpret_cast<ulonglong2*>(cp) = v0;
            *reinterpret_cast<ulonglong2*>(cp + 4) = v1;
        }
    }
}

// ---------------- epilogue / small kernels -------------------------------------
__global__ void epilogue(const float* __restrict__ T, long long sliceT,
                         const float* __restrict__ bias, const float* __restrict__ R,
                         float* __restrict__ dst, int n)
{
    int i = blockIdx.x * 256 + threadIdx.x;
    if (i >= n * DIM) return;
    int c = i % DIM;
    float v = T[i] + T[i + sliceT] + T[i + 2 * sliceT] + T[i + 3 * sliceT] + bias[c];
    v = v > 0.f ? v : 0.f;
    if (R) v += R[i];
    dst[i] = v;
}
__global__ void pooldiag(float* __restrict__ out)
{
    int i = blockIdx.x * 256 + threadIdx.x;
    if (i < KP0) out[(size_t)i * KP0 + i] = 1.0f;
}
__global__ void scores_kernel(const float* __restrict__ X, int n,
                              const float* __restrict__ pw, const float* __restrict__ pb,
                              float* __restrict__ out)
{
    int row = blockIdx.x * 8 + (threadIdx.x >> 5);
    int lane = threadIdx.x & 31;
    if (row >= n) return;
    float s = 0.f;
    for (int c = lane; c < DIM; c += 32) s += X[(size_t)row * DIM + c] * pw[c];
#pragma unroll
    for (int o = 16; o > 0; o >>= 1) s += __shfl_down_sync(0xffffffffu, s, o);
    if (lane == 0) {
        float z = (s + pb[0]) * 0.01f;
        out[row] = 1.0f / (1.0f + expf(-z));
    }
}
__global__ void topk_sort(const float* __restrict__ scores, int n,
                          int* __restrict__ idx_out, float* __restrict__ val_out)
{
    __shared__ unsigned long long keys[4096];
    int tid = threadIdx.x;
    for (int i = tid; i < 4096; i += 1024) {
        unsigned long long k = 0ull;
        if (i < n) {
            unsigned int fb = __float_as_uint(scores[i]);
            k = ((unsigned long long)fb << 12) | (unsigned int)(4095 - i);
        }
        keys[i] = k;
    }
    __syncthreads();
    for (int k = 2; k <= 4096; k <<= 1) {
        for (int j = k >> 1; j > 0; j >>= 1) {
            for (int t = tid; t < 4096; t += 1024) {
                int ixj = t ^ j;
                if (ixj > t) {
                    bool desc = ((t & k) == 0);
                    unsigned long long a = keys[t];
                    unsigned long long b = keys[ixj];
                    if ((a < b) == desc) {
                        keys[t] = b;
                        keys[ixj] = a;
                    }
                }
            }
            __syncthreads();
        }
    }
    for (int i = tid; i < 4096; i += 1024) {
        unsigned long long kk = keys[i];
        idx_out[i] = 4095 - (int)(kk & 0xFFFull);
        val_out[i] = __uint_as_float((unsigned int)(kk >> 12));
    }
}
__global__ void gather_scale(const float* __restrict__ X, const int* __restrict__ idx,
                             const float* __restrict__ vals, float* __restrict__ out, int kn)
{
    int i = blockIdx.x * 256 + threadIdx.x;
    if (i >= kn * DIM) return;
    int r = i / DIM;
    int c = i - r * DIM;
    out[i] = X[(size_t)idx[r] * DIM + c] * vals[r];
}
__global__ void compose_idx(const int* __restrict__ a, const int* __restrict__ b,
                            int* __restrict__ out, int n)
{
    int i = blockIdx.x * 256 + threadIdx.x;
    if (i < n) out[i] = a[b[i]];
}

// -----------------------------------------------------------------------------
extern "C" void kernel_launch(void* const* d_in, const int* in_sizes, int n_in,
                              void* d_out, int out_size)
{
    const float* A = (const float*)d_in[0];
    const float* X = (const float*)d_in[1];
    const float* w_start = (const float*)d_in[2];
    const float* b_start = (const float*)d_in[3];
    const float* w_down0 = (const float*)d_in[4];
    const float* b_down0 = (const float*)d_in[5];
    const float* w_down1 = (const float*)d_in[6];
    const float* b_down1 = (const float*)d_in[7];
    const float* p_w0 = (const float*)d_in[8];
    const float* p_b0 = (const float*)d_in[9];
    const float* p_w1 = (const float*)d_in[10];
    const float* p_b1 = (const float*)d_in[11];
    const float* w_bottom = (const float*)d_in[12];
    const float* b_bottom = (const float*)d_in[13];
    const float* w_up0 = (const float*)d_in[14];
    const float* b_up0 = (const float*)d_in[15];
    const float* w_up1 = (const float*)d_in[16];
    const float* b_up1 = (const float*)d_in[17];
    const float* w_end = (const float*)d_in[18];
    const float* b_end = (const float*)d_in[19];
    float* out = (float*)d_out;

    u32 *AFh, *AFl, *G1h, *G1l, *U1h, *U1l, *G2h, *G2l, *U0h, *U0l;
    u32 *BFh, *BFl, *XAh, *XAl, *XBh, *XBl, *mx;
    float *P, *Q, *AXc, *X0, *Xd0, *Xd1, *Xp0, *Xp1, *Xb, *Xu, *XcL;
    float *sc, *v0, *v1;
    int *i0, *i1, *i01;
    cudaGetSymbolAddress((void**)&AFh, g_AFh);
    cudaGetSymbolAddress((void**)&AFl, g_AFl);
    cudaGetSymbolAddress((void**)&G1h, g_G1h);
    cudaGetSymbolAddress((void**)&G1l, g_G1l);
    cudaGetSymbolAddress((void**)&U1h, g_U1h);
    cudaGetSymbolAddress((void**)&U1l, g_U1l);
    cudaGetSymbolAddress((void**)&G2h, g_G2h);
    cudaGetSymbolAddress((void**)&G2l, g_G2l);
    cudaGetSymbolAddress((void**)&U0h, g_U0h);
    cudaGetSymbolAddress((void**)&U0l, g_U0l);
    cudaGetSymbolAddress((void**)&BFh, g_BFh);
    cudaGetSymbolAddress((void**)&BFl, g_BFl);
    cudaGetSymbolAddress((void**)&XAh, g_XAh);
    cudaGetSymbolAddress((void**)&XAl, g_XAl);
    cudaGetSymbolAddress((void**)&XBh, g_XBh);
    cudaGetSymbolAddress((void**)&XBl, g_XBl);
    cudaGetSymbolAddress((void**)&mx, g_mx);
    cudaGetSymbolAddress((void**)&P, g_P);
    cudaGetSymbolAddress((void**)&Q, g_Q);
    cudaGetSymbolAddress((void**)&AXc, g_AXc);
    cudaGetSymbolAddress((void**)&X0, g_X0);
    cudaGetSymbolAddress((void**)&Xd0, g_Xd0);
    cudaGetSymbolAddress((void**)&Xd1, g_Xd1);
    cudaGetSymbolAddress((void**)&Xp0, g_Xp0);
    cudaGetSymbolAddress((void**)&Xp1, g_Xp1);
    cudaGetSymbolAddress((void**)&Xb, g_Xb);
    cudaGetSymbolAddress((void**)&Xu, g_Xu);
    cudaGetSymbolAddress((void**)&XcL, g_XcL);
    cudaGetSymbolAddress((void**)&sc, g_scores);
    cudaGetSymbolAddress((void**)&i0, g_idx0);
    cudaGetSymbolAddress((void**)&v0, g_val0);
    cudaGetSymbolAddress((void**)&i1, g_idx1);
    cudaGetSymbolAddress((void**)&v1, g_val1);
    cudaGetSymbolAddress((void**)&i01, g_idx01);

    const long long PS = (long long)NN * DIM;
    const long long PSX = (long long)NN * 2 * DIM;

    auto tg = [](long long n) { return (unsigned)((n + 255) / 256); };
    auto mg = [&](const u32* ah, const u32* al, const u32* bh, const u32* bl,
                  int KB16, float* C, int ldc, long long cSlice, int M,
                  const u32* mxB) {
        int cps = (KB16 + 3) / 4;
        dim3 g(5, (unsigned)((M + 127) / 128), 4);
        gemm_mma16<<<g, 128>>>(ah, al, bh, bl, KB16, C, ldc, cSlice, M, DIM, cps,
                               nullptr, mxB);
    };
    auto fg = [&](const float* A_, long long sA, int nSl, int lda, const float* B_,
                  float* C_, int M_, int K_) {
        int kChunk = (((K_ + 3) / 4 + 15) / 16) * 16;
        dim3 g(5, (unsigned)((M_ + 127) / 128), 4);
        gemmBig<<<g, 128>>>(A_, sA, nSl, lda, B_, DIM, C_, DIM, PS, M_, kChunk, K_);
    };
    auto eg = [](int n) { return (unsigned)((n * DIM + 255) / 256); };

    const long long slotsB512 = (long long)(DIM / 8) * KB_A * 64;
    const long long slotsB464 = (long long)(DIM / 8) * KB_1 * 64;
    const long long slotsB336 = (long long)(DIM / 8) * KB_2 * 64;
    const long long slotsXB = (long long)(MP0 / 8) * KB_D * 64;

    // scale slots: 0:X 1:X0 2:Xp0 3:Xp1 4:Xb 5:Xu 6:XcL
    zeroMx<<<1, 32>>>(mx);

    // one-time: A fragments (unscaled; A ~ U(0,1)), X B-fragments
    afragRow16<<<NN, 256>>>(A, NN, nullptr, nullptr, NN, KB_A, nullptr, AFh, AFl);
    absmaxK<<<512, 256>>>(X, (long long)NN * DIM, mx + 0);
    bfrag16<<<tg(slotsB512), 256>>>(X, DIM, NN, KB_A, 0, mx + 0, BFh, BFl, slotsB512);

    // start: X0 = relu((A@X)@w_start + b)
    mg(AFh, AFl, BFh, BFl, KB_A, P, DIM, PS, NN, mx + 0);
    fg(P, PS, 4, DIM, w_start, Q, NN, DIM);
    epilogue<<<eg(NN), 256>>>(Q, PS, b_start, nullptr, X0, NN);
    cudaMemcpyAsync(out + OFF_START, X0, (size_t)NN * DIM * sizeof(float),
                    cudaMemcpyDeviceToDevice, 0);

    // Xd0 = gcn(A, X0, w_down0); A@X0 slices kept in AXc right half
    absmaxK<<<512, 256>>>(X0, (long long)NN * DIM, mx + 1);
    bfrag16<<<tg(slotsB512), 256>>>(X0, DIM, NN, KB_A, 0, mx + 1, BFh, BFl, slotsB512);
    mg(AFh, AFl, BFh, BFl, KB_A, AXc + DIM, 2 * DIM, PSX, NN, mx + 1);
    fg(AXc + DIM, PSX, 4, 2 * DIM, w_down0, Q, NN, DIM);
    epilogue<<<eg(NN), 256>>>(Q, PS, b_down0, nullptr, Xd0, NN);

    // pool 0
    scores_kernel<<<(NN + 7) / 8, 256>>>(Xd0, NN, p_w0, p_b0, sc);
    topk_sort<<<1, 1024>>>(sc, NN, i0, v0);
    gather_scale<<<tg((long long)KP0 * DIM), 256>>>(Xd0, i0, v0, Xp0, KP0);
    afragRow16<<<KP0, 256>>>(A, NN, i0, i0, KP0, KB_1, nullptr, G1h, G1l);
    afragRow16<<<NN, 256>>>(A, NN, nullptr, i0, KP0, KB_1, nullptr, U1h, U1l);

    // Xd1 = gcn(A1, Xp0, w_down1)
    absmaxK<<<512, 256>>>(Xp0, (long long)KP0 * DIM, mx + 2);
    bfrag16<<<tg(slotsB464), 256>>>(Xp0, DIM, KP0, KB_1, 0, mx + 2, BFh, BFl, slotsB464);
    mg(G1h, G1l, BFh, BFl, KB_1, P, DIM, PS, KP0, mx + 2);
    fg(P, PS, 4, DIM, w_down1, Q, KP0, DIM);
    epilogue<<<eg(KP0), 256>>>(Q, PS, b_down1, nullptr, Xd1, KP0);

    // pool frags of Xp0 (both sides scaled by mx+2)
    afragRow16<<<KP0, 256>>>(Xp0, DIM, nullptr, nullptr, DIM, KB_D, mx + 2, XAh, XAl);
    bfrag16<<<tg(slotsXB), 256>>>(Xp0, DIM, KP0, KB_D, 1, mx + 2, XBh, XBl, slotsXB);

    // pool 1
    scores_kernel<<<(KP0 + 7) / 8, 256>>>(Xd1, KP0, p_w1, p_b1, sc);
    topk_sort<<<1, 1024>>>(sc, KP0, i1, v1);
    gather_scale<<<tg((long long)KP1 * DIM), 256>>>(Xd1, i1, v1, Xp1, KP1);
    compose_idx<<<tg(KP1), 256>>>(i0, i1, i01, KP1);
    afragRow16<<<KP1, 256>>>(A, NN, i01, i01, KP1, KB_2, nullptr, G2h, G2l);
    afragRow16<<<KP0, 256>>>(A, NN, i0, i01, KP1, KB_2, nullptr, U0h, U0l);

    // bottom: Xb = gcn(A2, Xp1, w_bottom)
    absmaxK<<<512, 256>>>(Xp1, (long long)KP1 * DIM, mx + 3);
    bfrag16<<<tg(slotsB336), 256>>>(Xp1, DIM, KP1, KB_2, 0, mx + 3, BFh, BFl, slotsB336);
    mg(G2h, G2l, BFh, BFl, KB_2, P, DIM, PS, KP1, mx + 3);
    fg(P, PS, 4, DIM, w_bottom, Q, KP1, DIM);
    epilogue<<<eg(KP1), 256>>>(Q, PS, b_bottom, nullptr, Xb, KP1);

    // up 0: Xu = gcn(A1, scatter(Xb), w_up0) + Xd1
    absmaxK<<<512, 256>>>(Xb, (long long)KP1 * DIM, mx + 4);
    bfrag16<<<tg(slotsB336), 256>>>(Xb, DIM, KP1, KB_2, 0, mx + 4, BFh, BFl, slotsB336);
    mg(U0h, U0l, BFh, BFl, KB_2, P, DIM, PS, KP0, mx + 4);
    fg(P, PS, 4, DIM, w_up0, Q, KP0, DIM);
    epilogue<<<eg(KP0), 256>>>(Q, PS, b_up0, Xd1, Xu, KP0);

    // up 1: XcL = gcn(A, scatter(Xu), w_up1) + Xd0
    absmaxK<<<512, 256>>>(Xu, (long long)KP0 * DIM, mx + 5);
    bfrag16<<<tg(slotsB464), 256>>>(Xu, DIM, KP0, KB_1, 0, mx + 5, BFh, BFl, slotsB464);
    mg(U1h, U1l, BFh, BFl, KB_1, P, DIM, PS, NN, mx + 5);
    fg(P, PS, 4, DIM, w_up1, Q, NN, DIM);
    epilogue<<<eg(NN), 256>>>(Q, PS, b_up1, Xd0, XcL, NN);

    // end: Xout = gcn(A, [XcL | X0], w_end); A@X0 reused from AXc right half
    absmaxK<<<512, 256>>>(XcL, (long long)NN * DIM, mx + 6);
    bfrag16<<<tg(slotsB512), 256>>>(XcL, DIM, NN, KB_A, 0, mx + 6, BFh, BFl, slotsB512);
    mg(AFh, AFl, BFh, BFl, KB_A, AXc, 2 * DIM, PSX, NN, mx + 6);
    fg(AXc, PSX, 4, 2 * DIM, w_end, Q, NN, 2 * DIM);
    epilogue<<<eg(NN), 256>>>(Q, PS, b_end, nullptr, out, NN);

    // pool_out = Xp0 @ Xp0^T (both operands scaled by mx+2), diag = 1
    {
        dim3 g((unsigned)((KP0 + 63) / 64), (unsigned)((KP0 + 127) / 128), 1);
        gemm_mma16<<<g, 128>>>(XAh, XAl, XBh, XBl, KB_D, out + OFF_POOL, KP0, 0,
                               KP0, KP0, KB_D, mx + 2, mx + 2);
    }
    pooldiag<<<tg(KP0), 256>>>(out + OFF_POOL);
}